// round 1
// baseline (speedup 1.0000x reference)
#include <cuda_runtime.h>
#include <cstdint>

// Qwen3MoeMLP: out = down( silu(x @ gate^T) * (x @ up^T) )
// T=8192, H=2048, I=768, fp32. Strategy: TF32 mma.sync with fp32 accumulate.
// Kernel 1: fused gate+up GEMM + SiLU*up epilogue -> g_hbuf [T, I] (fp32 scratch)
// Kernel 2: down GEMM -> out [T, H]

#define T_DIM 8192
#define H_DIM 2048
#define I_DIM 768

#define BK 32
#define SK 36           // padded smem row stride (floats): conflict-free + 16B aligned

// Scratch for intermediate h = silu(gate)*up. Static device global (no allocs).
__device__ __align__(256) float g_hbuf[(size_t)T_DIM * I_DIM];

__device__ __forceinline__ unsigned f2tf(float f) {
    unsigned u;
    asm("cvt.rna.tf32.f32 %0, %1;" : "=r"(u) : "f"(f));
    return u;
}

__device__ __forceinline__ void cp16(void* s, const void* g) {
    unsigned sa = (unsigned)__cvta_generic_to_shared(s);
    asm volatile("cp.async.cg.shared.global [%0], [%1], 16;\n" :: "r"(sa), "l"(g));
}
__device__ __forceinline__ void cp_commit() {
    asm volatile("cp.async.commit_group;\n" ::);
}
template <int N>
__device__ __forceinline__ void cp_wait() {
    asm volatile("cp.async.wait_group %0;\n" :: "n"(N));
}

__device__ __forceinline__ void mma8(float* c, const unsigned* a, const unsigned* b) {
    asm volatile(
        "mma.sync.aligned.m16n8k8.row.col.f32.tf32.tf32.f32 "
        "{%0,%1,%2,%3}, {%4,%5,%6,%7}, {%8,%9}, {%0,%1,%2,%3};\n"
        : "+f"(c[0]), "+f"(c[1]), "+f"(c[2]), "+f"(c[3])
        : "r"(a[0]), "r"(a[1]), "r"(a[2]), "r"(a[3]), "r"(b[0]), "r"(b[1]));
}

// ============================================================================
// Kernel 1: gate+up fused.  C tile: BM=128 x BN=64 (per projection).
// 8 warps: wm = warp&3 (M, 4x32), wn = warp>>2 (N, 2x32).
// Each warp: 2 m16 tiles x 4 n8 tiles per projection.
// ============================================================================
__global__ void __launch_bounds__(256, 2)
gateup_kernel(const float* __restrict__ X,
              const float* __restrict__ Wg,
              const float* __restrict__ Wu)
{
    extern __shared__ float smp[];
    float* As = smp;                     // [2][128][SK]
    float* Bg = smp + 2 * 128 * SK;      // [2][64][SK]
    float* Bu = Bg + 2 * 64 * SK;        // [2][64][SK]

    const int tid  = threadIdx.x;
    const int lane = tid & 31;
    const int warp = tid >> 5;
    const int wm = warp & 3;
    const int wn = warp >> 2;
    const int g  = lane >> 2;            // groupID
    const int tg = lane & 3;             // threadID_in_group

    const int bm = blockIdx.x * 128;
    const int bn = blockIdx.y * 64;

    const int lr = tid >> 3;             // 0..31 (load row)
    const int lc = (tid & 7) * 4;        // 0..28 (load col, floats)

    float accg[2][4][4];
    float accu[2][4][4];
#pragma unroll
    for (int i = 0; i < 2; i++)
#pragma unroll
        for (int j = 0; j < 4; j++)
#pragma unroll
            for (int k = 0; k < 4; k++) { accg[i][j][k] = 0.f; accu[i][j][k] = 0.f; }

    auto load_stage = [&](int st, int kt) {
        const int k0 = kt * BK;
        float* as = As + st * 128 * SK;
#pragma unroll
        for (int i = 0; i < 4; i++) {
            const int r = lr + 32 * i;
            cp16(as + r * SK + lc, X + (size_t)(bm + r) * H_DIM + k0 + lc);
        }
        float* bgs = Bg + st * 64 * SK;
        float* bus = Bu + st * 64 * SK;
#pragma unroll
        for (int i = 0; i < 2; i++) {
            const int r = lr + 32 * i;
            cp16(bgs + r * SK + lc, Wg + (size_t)(bn + r) * H_DIM + k0 + lc);
            cp16(bus + r * SK + lc, Wu + (size_t)(bn + r) * H_DIM + k0 + lc);
        }
    };

    auto compute = [&](int st) {
        const float* as  = As + st * 128 * SK;
        const float* bgs = Bg + st * 64 * SK;
        const float* bus = Bu + st * 64 * SK;
#pragma unroll
        for (int k8 = 0; k8 < BK / 8; k8++) {
            const int kk = k8 * 8;
            unsigned a[2][4];
#pragma unroll
            for (int t = 0; t < 2; t++) {
                const float* ap = as + (size_t)(wm * 32 + t * 16) * SK + kk;
                a[t][0] = f2tf(ap[(size_t)g * SK + tg]);
                a[t][1] = f2tf(ap[(size_t)(g + 8) * SK + tg]);
                a[t][2] = f2tf(ap[(size_t)g * SK + tg + 4]);
                a[t][3] = f2tf(ap[(size_t)(g + 8) * SK + tg + 4]);
            }
#pragma unroll
            for (int t = 0; t < 4; t++) {
                const int n = wn * 32 + t * 8 + g;
                unsigned bgf[2], buf2[2];
                bgf[0]  = f2tf(bgs[(size_t)n * SK + kk + tg]);
                bgf[1]  = f2tf(bgs[(size_t)n * SK + kk + tg + 4]);
                buf2[0] = f2tf(bus[(size_t)n * SK + kk + tg]);
                buf2[1] = f2tf(bus[(size_t)n * SK + kk + tg + 4]);
#pragma unroll
                for (int m = 0; m < 2; m++) {
                    mma8(accg[m][t], a[m], bgf);
                    mma8(accu[m][t], a[m], buf2);
                }
            }
        }
    };

    const int KT = H_DIM / BK;  // 64
    load_stage(0, 0);
    cp_commit();

    for (int kt = 0; kt < KT; ++kt) {
        if (kt + 1 < KT) {
            load_stage((kt + 1) & 1, kt + 1);
            cp_commit();
            cp_wait<1>();
        } else {
            cp_wait<0>();
        }
        __syncthreads();
        compute(kt & 1);
        __syncthreads();
    }

    // Epilogue: h = silu(gate) * up  -> g_hbuf
#pragma unroll
    for (int tm = 0; tm < 2; tm++) {
#pragma unroll
        for (int tn = 0; tn < 4; tn++) {
            const int r0 = bm + wm * 32 + tm * 16 + g;
            const int c0 = bn + wn * 32 + tn * 8 + 2 * tg;
            float h[4];
#pragma unroll
            for (int i = 0; i < 4; i++) {
                const float gv = accg[tm][tn][i];
                const float uv = accu[tm][tn][i];
                h[i] = gv * uv / (1.0f + __expf(-gv));
            }
            *(float2*)(g_hbuf + (size_t)r0 * I_DIM + c0)       = make_float2(h[0], h[1]);
            *(float2*)(g_hbuf + (size_t)(r0 + 8) * I_DIM + c0) = make_float2(h[2], h[3]);
        }
    }
}

// ============================================================================
// Kernel 2: down projection.  C tile: BM=128 x BN=128.
// 8 warps: wm = warp&3 (M, 4x32), wn = warp>>2 (N, 2x64).
// Each warp: 2 m16 tiles x 8 n8 tiles.
// ============================================================================
__global__ void __launch_bounds__(256, 2)
down_kernel(const float* __restrict__ Wd, float* __restrict__ Out)
{
    extern __shared__ float smp[];
    float* As = smp;                     // [2][128][SK]
    float* Bs = smp + 2 * 128 * SK;      // [2][128][SK]

    const int tid  = threadIdx.x;
    const int lane = tid & 31;
    const int warp = tid >> 5;
    const int wm = warp & 3;
    const int wn = warp >> 2;
    const int g  = lane >> 2;
    const int tg = lane & 3;

    const int bm = blockIdx.x * 128;
    const int bn = blockIdx.y * 128;

    const int lr = tid >> 3;
    const int lc = (tid & 7) * 4;

    float acc[2][8][4];
#pragma unroll
    for (int i = 0; i < 2; i++)
#pragma unroll
        for (int j = 0; j < 8; j++)
#pragma unroll
            for (int k = 0; k < 4; k++) acc[i][j][k] = 0.f;

    auto load_stage = [&](int st, int kt) {
        const int k0 = kt * BK;
        float* as = As + st * 128 * SK;
        float* bs = Bs + st * 128 * SK;
#pragma unroll
        for (int i = 0; i < 4; i++) {
            const int r = lr + 32 * i;
            cp16(as + r * SK + lc, g_hbuf + (size_t)(bm + r) * I_DIM + k0 + lc);
            cp16(bs + r * SK + lc, Wd + (size_t)(bn + r) * I_DIM + k0 + lc);
        }
    };

    auto compute = [&](int st) {
        const float* as = As + st * 128 * SK;
        const float* bs = Bs + st * 128 * SK;
#pragma unroll
        for (int k8 = 0; k8 < BK / 8; k8++) {
            const int kk = k8 * 8;
            unsigned a[2][4];
#pragma unroll
            for (int t = 0; t < 2; t++) {
                const float* ap = as + (size_t)(wm * 32 + t * 16) * SK + kk;
                a[t][0] = f2tf(ap[(size_t)g * SK + tg]);
                a[t][1] = f2tf(ap[(size_t)(g + 8) * SK + tg]);
                a[t][2] = f2tf(ap[(size_t)g * SK + tg + 4]);
                a[t][3] = f2tf(ap[(size_t)(g + 8) * SK + tg + 4]);
            }
            unsigned b[8][2];
#pragma unroll
            for (int t = 0; t < 8; t++) {
                const int n = wn * 64 + t * 8 + g;
                b[t][0] = f2tf(bs[(size_t)n * SK + kk + tg]);
                b[t][1] = f2tf(bs[(size_t)n * SK + kk + tg + 4]);
            }
#pragma unroll
            for (int t = 0; t < 8; t++)
#pragma unroll
                for (int m = 0; m < 2; m++)
                    mma8(acc[m][t], a[m], b[t]);
        }
    };

    const int KT = I_DIM / BK;  // 24
    load_stage(0, 0);
    cp_commit();

    for (int kt = 0; kt < KT; ++kt) {
        if (kt + 1 < KT) {
            load_stage((kt + 1) & 1, kt + 1);
            cp_commit();
            cp_wait<1>();
        } else {
            cp_wait<0>();
        }
        __syncthreads();
        compute(kt & 1);
        __syncthreads();
    }

#pragma unroll
    for (int tm = 0; tm < 2; tm++) {
#pragma unroll
        for (int tn = 0; tn < 8; tn++) {
            const int r0 = bm + wm * 32 + tm * 16 + g;
            const int c0 = bn + wn * 64 + tn * 8 + 2 * tg;
            *(float2*)(Out + (size_t)r0 * H_DIM + c0) =
                make_float2(acc[tm][tn][0], acc[tm][tn][1]);
            *(float2*)(Out + (size_t)(r0 + 8) * H_DIM + c0) =
                make_float2(acc[tm][tn][2], acc[tm][tn][3]);
        }
    }
}

// ============================================================================
// Launch
// ============================================================================
extern "C" void kernel_launch(void* const* d_in, const int* in_sizes, int n_in,
                              void* d_out, int out_size)
{
    const float* x  = (const float*)d_in[0];
    const float* wg = (const float*)d_in[1];
    const float* wu = (const float*)d_in[2];
    const float* wd = (const float*)d_in[3];
    float* out = (float*)d_out;

    const int smem_bytes = (2 * 128 * SK + 2 * 64 * SK * 2) * (int)sizeof(float); // 73728
    cudaFuncSetAttribute(gateup_kernel, cudaFuncAttributeMaxDynamicSharedMemorySize, smem_bytes);
    cudaFuncSetAttribute(down_kernel,   cudaFuncAttributeMaxDynamicSharedMemorySize, smem_bytes);

    dim3 grid1(T_DIM / 128, I_DIM / 64);   // 64 x 12
    gateup_kernel<<<grid1, 256, smem_bytes>>>(x, wg, wu);

    dim3 grid2(T_DIM / 128, H_DIM / 128);  // 64 x 16
    down_kernel<<<grid2, 256, smem_bytes>>>(wd, out);
}